// round 12
// baseline (speedup 1.0000x reference)
#include <cuda_runtime.h>
#include <cstdint>

#define KDIM   4096
#define BATCH  16384
#define CRC    24
#define OUTW   (KDIM + CRC)        // 4120
#define NBLOCK 2048                // one row per warp, 8 warps per block
#define NPACK  32                  // blocks that also pack masks

// Packed g_mat masks: bit j of g_masks[k] = (g_mat[k][j] != 0)
__device__ uint32_t g_masks[KDIM];
// Saturating ready counter; masks are a pure function of the constant g_mat,
// so re-packing identical values while others read is benign.
__device__ unsigned int g_ready;

__global__ void __launch_bounds__(256, 8)   // pin regs<=32: guarantee 8 CTAs/SM
crc_encode_fused(const float* __restrict__ in,
                 const float* __restrict__ g_mat,
                 float* __restrict__ out) {
    __shared__ uint4 smasks[KDIM / 4];        // 16 KB
    __shared__ uint32_t words[104];           // pack scratch (96 used + pad)

    const int tid  = threadIdx.x;
    const int lane = tid & 31;
    const int warp = tid >> 5;
    const int bid  = blockIdx.x;

    // ---- Blocks 0..31: pack 128 masks each (ballot-based, coalesced) ----
    if (bid < NPACK) {
        const int base = bid * (128 * CRC);   // 3072 floats per pack block
        #pragma unroll
        for (int r = 0; r < 12; r++) {
            int idx = r * 256 + tid;
            float v = g_mat[base + idx];
            unsigned b = __ballot_sync(0xFFFFFFFFu, v != 0.0f);
            if (lane == 0) words[idx >> 5] = b;
        }
        __syncthreads();
        if (tid < 128) {
            int bitpos = tid * CRC;
            uint32_t lo = words[bitpos >> 5];
            uint32_t hi = words[(bitpos >> 5) + 1];
            g_masks[bid * 128 + tid] =
                __funnelshift_r(lo, hi, bitpos & 31) & 0x00FFFFFFu;
        }
        __threadfence();
        __syncthreads();
        if (tid == 0) atomicAdd(&g_ready, 1u);
    }

    // ---- All blocks: wait until all NPACK pack blocks have published ----
    // Safe: blocks 0..31 are wave-1 resident and never spin before packing.
    if (tid == 0) {
        while (atomicAdd(&g_ready, 0u) < NPACK)
            __nanosleep(64);
    }
    __syncthreads();

    // ---- Load mask table to shared ----
    const uint4* gm4 = reinterpret_cast<const uint4*>(g_masks);
    #pragma unroll
    for (int i = tid; i < KDIM / 4; i += 256)
        smasks[i] = gm4[i];
    __syncthreads();

    // ---- One row per warp: fused copy + CRC ----
    const int row = bid * 8 + warp;

    const float4* __restrict__ inrow =
        reinterpret_cast<const float4*>(in + (size_t)row * KDIM);
    float4* __restrict__ outrow =
        reinterpret_cast<float4*>(out + (size_t)row * OUTW);

    uint32_t acc = 0;

    // 4096 floats / warp = 1024 float4 / warp = 32 float4 per lane.
    #pragma unroll 16
    for (int it = 0; it < 32; it++) {
        const int f = it * 32 + lane;
        float4 v = inrow[f];
        outrow[f] = v;
        uint4 m = smasks[f];
        if (v.x != 0.0f) acc ^= m.x;
        if (v.y != 0.0f) acc ^= m.y;
        if (v.z != 0.0f) acc ^= m.z;
        if (v.w != 0.0f) acc ^= m.w;
    }

    // XOR-reduce across the warp
    #pragma unroll
    for (int o = 16; o > 0; o >>= 1)
        acc ^= __shfl_xor_sync(0xFFFFFFFFu, acc, o);

    if (lane < CRC)
        out[(size_t)row * OUTW + KDIM + lane] = (float)((acc >> lane) & 1u);
}

extern "C" void kernel_launch(void* const* d_in, const int* in_sizes, int n_in,
                              void* d_out, int out_size) {
    const float* bits  = (const float*)d_in[0];   // [BATCH, KDIM]
    const float* g_mat = (const float*)d_in[1];   // [KDIM, CRC]
    float* out = (float*)d_out;                   // [BATCH, OUTW]

    crc_encode_fused<<<NBLOCK, 256>>>(bits, g_mat, out);
}

// round 13
// speedup vs baseline: 1.0098x; 1.0098x over previous
#include <cuda_runtime.h>
#include <cstdint>

#define KDIM   4096
#define BATCH  16384
#define CRC    24
#define OUTW   (KDIM + CRC)        // 4120
#define NBLOCK 2048                // one row per warp, 8 warps per block
#define NPACK  32                  // blocks that also pack masks

// Packed g_mat masks: bit j of g_masks[k] = (g_mat[k][j] != 0)
__device__ uint32_t g_masks[KDIM];
// Saturating ready counter; masks are a pure function of the constant g_mat,
// so re-packing identical values while others read is benign.
__device__ unsigned int g_ready;

__global__ void __launch_bounds__(256) crc_encode_fused(const float* __restrict__ in,
                                                        const float* __restrict__ g_mat,
                                                        float* __restrict__ out) {
    __shared__ uint4 smasks[KDIM / 4];        // 16 KB
    __shared__ uint32_t words[104];           // pack scratch (96 used + pad)

    const int tid  = threadIdx.x;
    const int lane = tid & 31;
    const int warp = tid >> 5;
    const int bid  = blockIdx.x;

    // ---- Blocks 0..31: pack 128 masks each (ballot-based, coalesced) ----
    if (bid < NPACK) {
        const int base = bid * (128 * CRC);   // 3072 floats per pack block
        #pragma unroll
        for (int r = 0; r < 12; r++) {
            int idx = r * 256 + tid;
            float v = g_mat[base + idx];
            unsigned b = __ballot_sync(0xFFFFFFFFu, v != 0.0f);
            if (lane == 0) words[idx >> 5] = b;
        }
        __syncthreads();
        if (tid < 128) {
            int bitpos = tid * CRC;
            uint32_t lo = words[bitpos >> 5];
            uint32_t hi = words[(bitpos >> 5) + 1];
            g_masks[bid * 128 + tid] =
                __funnelshift_r(lo, hi, bitpos & 31) & 0x00FFFFFFu;
        }
        __threadfence();
        __syncthreads();
        if (tid == 0) atomicAdd(&g_ready, 1u);
    }

    // ---- All blocks: wait until all NPACK pack blocks have published ----
    // Safe: blocks 0..31 are wave-1 resident and never spin before packing.
    if (tid == 0) {
        while (atomicAdd(&g_ready, 0u) < NPACK)
            __nanosleep(64);
    }
    __syncthreads();

    // ---- Load mask table to shared ----
    const uint4* gm4 = reinterpret_cast<const uint4*>(g_masks);
    #pragma unroll
    for (int i = tid; i < KDIM / 4; i += 256)
        smasks[i] = gm4[i];
    __syncthreads();

    // ---- One row per warp: fused copy + CRC ----
    const int row = bid * 8 + warp;

    const float4* __restrict__ inrow =
        reinterpret_cast<const float4*>(in + (size_t)row * KDIM);
    float4* __restrict__ outrow =
        reinterpret_cast<float4*>(out + (size_t)row * OUTW);

    uint32_t acc = 0;

    // 4096 floats / warp = 1024 float4 / warp = 32 float4 per lane
    #pragma unroll 8
    for (int it = 0; it < 32; it++) {
        const int f = it * 32 + lane;
        float4 v = inrow[f];
        outrow[f] = v;
        uint4 m = smasks[f];
        if (v.x != 0.0f) acc ^= m.x;
        if (v.y != 0.0f) acc ^= m.y;
        if (v.z != 0.0f) acc ^= m.z;
        if (v.w != 0.0f) acc ^= m.w;
    }

    // XOR-reduce across the warp
    #pragma unroll
    for (int o = 16; o > 0; o >>= 1)
        acc ^= __shfl_xor_sync(0xFFFFFFFFu, acc, o);

    if (lane < CRC)
        out[(size_t)row * OUTW + KDIM + lane] = (float)((acc >> lane) & 1u);
}

extern "C" void kernel_launch(void* const* d_in, const int* in_sizes, int n_in,
                              void* d_out, int out_size) {
    const float* bits  = (const float*)d_in[0];   // [BATCH, KDIM]
    const float* g_mat = (const float*)d_in[1];   // [KDIM, CRC]
    float* out = (float*)d_out;                   // [BATCH, OUTW]

    crc_encode_fused<<<NBLOCK, 256>>>(bits, g_mat, out);
}